// round 14
// baseline (speedup 1.0000x reference)
#include <cuda_runtime.h>
#include <cuda_fp16.h>
#include <stdint.h>

// Problem constants (fixed shapes per reference_code)
#define NN 100000
#define EE 1600000
#define D  32
#define CHUNK 1024
#define NCH ((NN + CHUNK - 1) / CHUNK)   // 98
#define FULL 0xffffffffu

// ---------------- scratch (static device globals; no allocation) ----------------
__device__ int    g_deg[NN];
__device__ float  g_dinv[NN];     // 1/sqrt(deg) (0 if deg==0)
__device__ float  g_sd[NN];       // sqrt(deg)
__device__ int    g_rowptr[NN + 1];
__device__ int    g_bsum[NCH];
__device__ int    g_boff[NCH];
__device__ int    g_rank[EE];     // per-edge rank within its row (from hist atomic)
__device__ int    g_col[EE];      // CSR column index only
// fp16 gather sources (accumulation stays fp32)
__device__ __half g_xs[NN * D];   // dinv-scaled x
__device__ float  g_h [NN * D];   // layer-1 output (true values, fp32)
__device__ __half g_hs[NN * D];   // dinv-scaled h
__device__ __half g_t1[NN * D];   // Tx1 in SCALED space

// ---------------- fp16 pack/unpack helpers ----------------
__device__ __forceinline__ void acc_add(float4& a, uint2 u) {
    float2 f0 = __half22float2(*reinterpret_cast<__half2*>(&u.x));
    float2 f1 = __half22float2(*reinterpret_cast<__half2*>(&u.y));
    a.x += f0.x; a.y += f0.y; a.z += f1.x; a.w += f1.y;
}
__device__ __forceinline__ uint2 pack_half4(float4 v) {
    __half2 h0 = __floats2half2_rn(v.x, v.y);
    __half2 h1 = __floats2half2_rn(v.z, v.w);
    uint2 u;
    u.x = *reinterpret_cast<unsigned*>(&h0);
    u.y = *reinterpret_cast<unsigned*>(&h1);
    return u;
}

// ---------------- build kernels ----------------
__global__ void k_zero_deg() {
    int i = blockIdx.x * blockDim.x + threadIdx.x;
    if (i < NN) g_deg[i] = 0;
}

// edge_index arrives as int32; 4 edges per thread. The atomic's return value is
// the edge's rank within its row -> saved for an atomic-free scatter later.
__global__ void k_hist(const int4* __restrict__ ei4) {
    int t = blockIdx.x * blockDim.x + threadIdx.x;
    if (t < EE / 4) {
        int4 r = ei4[t];
        int4 c = ei4[EE / 4 + t];
        int e = t * 4;
        if (r.x != c.x) g_rank[e + 0] = atomicAdd(&g_deg[r.x], 1);
        if (r.y != c.y) g_rank[e + 1] = atomicAdd(&g_deg[r.y], 1);
        if (r.z != c.z) g_rank[e + 2] = atomicAdd(&g_deg[r.z], 1);
        if (r.w != c.w) g_rank[e + 3] = atomicAdd(&g_deg[r.w], 1);
    }
}

// ---- parallel 3-phase scan (phase 1 also emits dinv & sqrt(deg)) ----
__global__ void __launch_bounds__(1024) k_scan1() {
    __shared__ int warp_sums[32];
    const int tid  = threadIdx.x;
    const int lane = tid & 31;
    const int wid  = tid >> 5;
    const int i    = blockIdx.x * CHUNK + tid;
    int v = (i < NN) ? g_deg[i] : 0;
    if (i < NN) {
        g_dinv[i] = (v > 0) ? rsqrtf((float)v) : 0.0f;
        g_sd[i]   = sqrtf((float)v);
    }
    int incl = v;
    #pragma unroll
    for (int off = 1; off < 32; off <<= 1) {
        int t = __shfl_up_sync(FULL, incl, off);
        if (lane >= off) incl += t;
    }
    if (lane == 31) warp_sums[wid] = incl;
    __syncthreads();
    if (wid == 0) {
        int s  = warp_sums[lane];
        int si = s;
        #pragma unroll
        for (int off = 1; off < 32; off <<= 1) {
            int t = __shfl_up_sync(FULL, si, off);
            if (lane >= off) si += t;
        }
        warp_sums[lane] = si - s;
        if (lane == 31) g_bsum[blockIdx.x] = si;
    }
    __syncthreads();
    int excl = warp_sums[wid] + (incl - v);
    if (i < NN) g_rowptr[i] = excl;
}

__global__ void __launch_bounds__(128) k_scan2() {
    __shared__ int warp_sums[4];
    const int tid  = threadIdx.x;
    const int lane = tid & 31;
    const int wid  = tid >> 5;
    int v = (tid < NCH) ? g_bsum[tid] : 0;
    int incl = v;
    #pragma unroll
    for (int off = 1; off < 32; off <<= 1) {
        int t = __shfl_up_sync(FULL, incl, off);
        if (lane >= off) incl += t;
    }
    if (lane == 31) warp_sums[wid] = incl;
    __syncthreads();
    int carry = 0;
    #pragma unroll
    for (int w = 0; w < 4; w++)
        if (w < wid) carry += warp_sums[w];
    int excl = carry + incl - v;
    if (tid < NCH) g_boff[tid] = excl;
    if (tid == NCH - 1) g_rowptr[NN] = excl + v;
}

__global__ void __launch_bounds__(1024) k_scan3() {
    int i = blockIdx.x * CHUNK + threadIdx.x;
    if (i < NN) g_rowptr[i] += g_boff[blockIdx.x];
}

// Atomic-free scatter: pos = rowptr[row] + rank. Writes ONLY the column index.
__global__ void k_scatter(const int4* __restrict__ ei4) {
    int t = blockIdx.x * blockDim.x + threadIdx.x;
    if (t < EE / 4) {
        int4 r = ei4[t];
        int4 c = ei4[EE / 4 + t];
        int e = t * 4;
        #pragma unroll
        for (int q = 0; q < 4; q++) {
            int rr = (q == 0) ? r.x : (q == 1) ? r.y : (q == 2) ? r.z : r.w;
            int cc = (q == 0) ? c.x : (q == 1) ? c.y : (q == 2) ? c.z : c.w;
            if (rr != cc) g_col[g_rowptr[rr] + g_rank[e + q]] = cc;
        }
    }
}

// ---- x_scaled = dinv ⊙ x, stored fp16 (coalesced: thread t -> element t) ----
__global__ void __launch_bounds__(256) k_pre(const float4* __restrict__ x4) {
    int t = blockIdx.x * blockDim.x + threadIdx.x;
    if (t < NN * 8) {
        float d = g_dinv[t >> 3];
        float4 v = x4[t];
        v.x *= d; v.y *= d; v.z *= d; v.w *= d;
        ((uint2*)g_xs)[t] = pack_half4(v);
    }
}

// ---------------- single-row gather (high-occupancy k_prop) ----------------
__device__ __forceinline__ float4 gather_row(int e0, int e1, int sub, int j,
                                             const uint2* __restrict__ src) {
    float4 acc = make_float4(0.f, 0.f, 0.f, 0.f);
    int e = e0 + sub;
    for (; e + 12 < e1; e += 16) {
        int c0 = g_col[e];
        int c1 = g_col[e + 4];
        int c2 = g_col[e + 8];
        int c3 = g_col[e + 12];
        uint2 u0 = src[c0 * 8 + j];
        uint2 u1 = src[c1 * 8 + j];
        uint2 u2 = src[c2 * 8 + j];
        uint2 u3 = src[c3 * 8 + j];
        acc_add(acc, u0);
        acc_add(acc, u1);
        acc_add(acc, u2);
        acc_add(acc, u3);
    }
    for (; e + 4 < e1; e += 8) {
        int c0 = g_col[e];
        int c1 = g_col[e + 4];
        uint2 u0 = src[c0 * 8 + j];
        uint2 u1 = src[c1 * 8 + j];
        acc_add(acc, u0);
        acc_add(acc, u1);
    }
    if (e < e1) {
        uint2 u = src[g_col[e] * 8 + j];
        acc_add(acc, u);
    }
    return acc;
}

// ---------------- dual-row interleaved gather (low-occupancy epi) ----------------
__device__ __forceinline__ void gather2(int e0A, int e1A, int e0B, int e1B,
                                        int sub, int j,
                                        const uint2* __restrict__ src,
                                        float4& accA, float4& accB) {
    accA = make_float4(0.f, 0.f, 0.f, 0.f);
    accB = make_float4(0.f, 0.f, 0.f, 0.f);
    int eA = e0A + sub;
    int eB = e0B + sub;
    int itA = (e1A - e0A + 15) >> 4;
    int itB = (e1B - e0B + 15) >> 4;
    int iters = (itA > itB) ? itA : itB;
    for (int it = 0; it < iters; it++) {
        int a0 = max(min(eA,      e1A - 1), 0);
        int a1 = max(min(eA + 4,  e1A - 1), 0);
        int a2 = max(min(eA + 8,  e1A - 1), 0);
        int a3 = max(min(eA + 12, e1A - 1), 0);
        int b0 = max(min(eB,      e1B - 1), 0);
        int b1 = max(min(eB + 4,  e1B - 1), 0);
        int b2 = max(min(eB + 8,  e1B - 1), 0);
        int b3 = max(min(eB + 12, e1B - 1), 0);
        int cA0 = g_col[a0], cA1 = g_col[a1], cA2 = g_col[a2], cA3 = g_col[a3];
        int cB0 = g_col[b0], cB1 = g_col[b1], cB2 = g_col[b2], cB3 = g_col[b3];
        uint2 uA0 = src[cA0 * 8 + j];
        uint2 uA1 = src[cA1 * 8 + j];
        uint2 uA2 = src[cA2 * 8 + j];
        uint2 uA3 = src[cA3 * 8 + j];
        uint2 uB0 = src[cB0 * 8 + j];
        uint2 uB1 = src[cB1 * 8 + j];
        uint2 uB2 = src[cB2 * 8 + j];
        uint2 uB3 = src[cB3 * 8 + j];
        if (eA      < e1A) acc_add(accA, uA0);
        if (eA + 4  < e1A) acc_add(accA, uA1);
        if (eA + 8  < e1A) acc_add(accA, uA2);
        if (eA + 12 < e1A) acc_add(accA, uA3);
        if (eB      < e1B) acc_add(accB, uB0);
        if (eB + 4  < e1B) acc_add(accB, uB1);
        if (eB + 8  < e1B) acc_add(accB, uB2);
        if (eB + 12 < e1B) acc_add(accB, uB3);
        eA += 16;
        eB += 16;
    }
}

__device__ __forceinline__ void reduce_subs(float4& acc) {
    #pragma unroll
    for (int off = 8; off <= 16; off <<= 1) {
        acc.x += __shfl_xor_sync(FULL, acc.x, off);
        acc.y += __shfl_xor_sync(FULL, acc.y, off);
        acc.z += __shfl_xor_sync(FULL, acc.z, off);
        acc.w += __shfl_xor_sync(FULL, acc.w, off);
    }
}

// ---------------- prop1: t1_scaled = -dinv^2 ⊙ (sum of scaled src rows) ----------------
__global__ void __launch_bounds__(256) k_prop(const uint2* __restrict__ src,
                                              uint2* __restrict__ dst) {
    int row  = (blockIdx.x * blockDim.x + threadIdx.x) >> 5;
    int lane = threadIdx.x & 31;
    if (row >= NN) return;
    int sub = lane >> 3, j = lane & 7;
    int e0 = g_rowptr[row], e1 = g_rowptr[row + 1];
    float4 acc = gather_row(e0, e1, sub, j, src);
    reduce_subs(acc);
    float di = g_dinv[row];
    float s  = -di * di;
    if (lane < 8) {
        acc.x *= s; acc.y *= s; acc.z *= s; acc.w *= s;
        dst[row * 8 + lane] = pack_half4(acc);   // lane == j here
    }
}

// ---------------- fused prop2 + epilogue, 2 rows per warp iteration ----------------
// Weights in SHARED memory (conflict-free stride-1) -> ~60 regs -> 4 CTAs/SM
// (32 warps) -> 2x outstanding gather loads vs the register-weight version.
// p_true = -dinv[row] * (sum of scaled t1 over cols);
// t1_true = t1_scaled * sqrt(deg);  out = h0@(W0-W2) + t1@W1 + p@(2W2) + b
__global__ void __launch_bounds__(256, 4) k_prop_epi(
        const uint2*  __restrict__ t1v,      // t1 SCALED fp16 (gather source)
        const __half* __restrict__ t1h,      // t1 SCALED scalar view
        const float*  __restrict__ h0,       // Tx0 rows (true, fp32)
        const float*  __restrict__ W,        // (3, 32, 32)
        const float*  __restrict__ b,
        const float*  __restrict__ resid,    // nullptr or residual rows
        float*        __restrict__ out,      // true output (fp32)
        __half*       __restrict__ outs,     // nullptr or dinv-scaled fp16 copy
        int do_relu) {
    __shared__ float sWc[D * D];
    __shared__ float sW1[D * D];
    __shared__ float sW2[D * D];
    __shared__ float sb[D];
    const int tid  = threadIdx.x;
    const int lane = tid & 31;
    const int sub  = lane >> 3, j = lane & 7;
    const int gw   = (blockIdx.x * blockDim.x + tid) >> 5;
    const int tot  = (gridDim.x * blockDim.x) >> 5;

    for (int i = tid; i < D * D; i += 256) {
        float a2 = W[2 * D * D + i];
        sWc[i] = W[i] - a2;
        sW1[i] = W[D * D + i];
        sW2[i] = 2.0f * a2;
    }
    if (tid < D) sb[tid] = b[tid];
    __syncthreads();
    const float bias = sb[lane];

    for (int rp = gw; rp < NN / 2; rp += tot) {
        const int rowA = rp * 2;
        const int rowB = rowA + 1;
        int e0A = g_rowptr[rowA], e1A = g_rowptr[rowA + 1];
        int e0B = e1A,            e1B = g_rowptr[rowB + 1];
        float4 accA, accB;
        gather2(e0A, e1A, e0B, e1B, sub, j, t1v, accA, accB);
        reduce_subs(accA);
        reduce_subs(accB);
        #pragma unroll
        for (int half = 0; half < 2; half++) {
            const int row = (half == 0) ? rowA : rowB;
            float4 acc   = (half == 0) ? accA : accB;
            float di = g_dinv[row];
            float sd = g_sd[row];
            float nd = -di;
            acc.x *= nd; acc.y *= nd; acc.z *= nd; acc.w *= nd;   // p_true chunk
            float hv = h0[row * D + lane];
            float tv = __half2float(t1h[row * D + lane]) * sd;     // unscale t1
            float o = bias;
            #pragma unroll
            for (int i = 0; i < D; i++) {
                float hi = __shfl_sync(FULL, hv, i);
                float ti = __shfl_sync(FULL, tv, i);
                float comp = ((i & 3) == 0) ? acc.x :
                             ((i & 3) == 1) ? acc.y :
                             ((i & 3) == 2) ? acc.z : acc.w;
                float pi = __shfl_sync(FULL, comp, i >> 2);
                o = fmaf(hi, sWc[i * D + lane], o);
                o = fmaf(ti, sW1[i * D + lane], o);
                o = fmaf(pi, sW2[i * D + lane], o);
            }
            if (do_relu) o = fmaxf(o, 0.0f);
            if (resid)   o += resid[row * D + lane];
            out[row * D + lane] = o;
            if (outs) outs[row * D + lane] = __float2half(di * o);
        }
    }
}

// ---------------- launch ----------------
extern "C" void kernel_launch(void* const* d_in, const int* in_sizes, int n_in,
                              void* d_out, int out_size) {
    const float* x  = (const float*)d_in[0];
    const int*   ei = (const int*)d_in[1];       // int32 edge_index (2, E)
    const float* W1 = (const float*)d_in[2];
    const float* b1 = (const float*)d_in[3];
    const float* W2 = (const float*)d_in[4];
    const float* b2 = (const float*)d_in[5];
    float*       out = (float*)d_out;

    void *p_xs, *p_h, *p_hs, *p_t1;
    cudaGetSymbolAddress(&p_xs, g_xs);
    cudaGetSymbolAddress(&p_h,  g_h);
    cudaGetSymbolAddress(&p_hs, g_hs);
    cudaGetSymbolAddress(&p_t1, g_t1);

    const int TB = 256;
    int gN  = (NN + TB - 1) / TB;
    int gE4 = (EE / 4 + TB - 1) / TB;
    int gV  = (NN * 8 + TB - 1) / TB;  // 4-float chunks
    int gProp = (NN + 7) / 8;          // one warp per row
    int gFuse = 592;                   // 148 SMs * 4 resident CTAs

    // ---- CSR build (col-only) ----
    k_zero_deg<<<gN, TB>>>();
    k_hist<<<gE4, TB>>>((const int4*)ei);
    k_scan1<<<NCH, 1024>>>();
    k_scan2<<<1, 128>>>();
    k_scan3<<<NCH, 1024>>>();
    k_scatter<<<gE4, TB>>>((const int4*)ei);
    k_pre<<<gV, TB>>>((const float4*)x);

    // ---- layer 1: h = relu(cheb(x; W1,b1)), plus scaled fp16 copy hs ----
    k_prop<<<gProp, TB>>>((const uint2*)p_xs, (uint2*)p_t1);
    k_prop_epi<<<gFuse, TB>>>((const uint2*)p_t1, (const __half*)p_t1,
                              x, W1, b1, (const float*)nullptr,
                              (float*)p_h, (__half*)p_hs, 1);

    // ---- layer 2 + residual: out = cheb(h; W2,b2) + x ----
    k_prop<<<gProp, TB>>>((const uint2*)p_hs, (uint2*)p_t1);
    k_prop_epi<<<gFuse, TB>>>((const uint2*)p_t1, (const __half*)p_t1,
                              (const float*)p_h, W2, b2,
                              x, out, (__half*)nullptr, 0);
}

// round 15
// speedup vs baseline: 1.4769x; 1.4769x over previous
#include <cuda_runtime.h>
#include <cuda_fp16.h>
#include <stdint.h>

// Problem constants (fixed shapes per reference_code)
#define NN 100000
#define EE 1600000
#define D  32
#define CHUNK 1024
#define NCH ((NN + CHUNK - 1) / CHUNK)   // 98
#define FULL 0xffffffffu

// ---------------- scratch (static device globals; no allocation) ----------------
__device__ int    g_deg[NN];
__device__ float  g_dinv[NN];     // 1/sqrt(deg) (0 if deg==0)
__device__ float  g_sd[NN];       // sqrt(deg)
__device__ int    g_rowptr[NN + 1];
__device__ int    g_bsum[NCH];
__device__ int    g_boff[NCH];
__device__ int    g_rank[EE];     // per-edge rank within its row (from hist atomic)
__device__ int    g_col[EE];      // CSR column index only
// fp16 gather sources (accumulation stays fp32)
__device__ __half g_xs[NN * D];   // dinv-scaled x
__device__ float  g_h [NN * D];   // layer-1 output (true values, fp32)
__device__ __half g_hs[NN * D];   // dinv-scaled h
__device__ __half g_t1[NN * D];   // Tx1 in SCALED space

// ---------------- fp16 pack/unpack helpers ----------------
__device__ __forceinline__ void acc_add(float4& a, uint2 u) {
    float2 f0 = __half22float2(*reinterpret_cast<__half2*>(&u.x));
    float2 f1 = __half22float2(*reinterpret_cast<__half2*>(&u.y));
    a.x += f0.x; a.y += f0.y; a.z += f1.x; a.w += f1.y;
}
__device__ __forceinline__ uint2 pack_half4(float4 v) {
    __half2 h0 = __floats2half2_rn(v.x, v.y);
    __half2 h1 = __floats2half2_rn(v.z, v.w);
    uint2 u;
    u.x = *reinterpret_cast<unsigned*>(&h0);
    u.y = *reinterpret_cast<unsigned*>(&h1);
    return u;
}

// ---------------- build kernels ----------------
__global__ void k_zero_deg() {
    int i = blockIdx.x * blockDim.x + threadIdx.x;
    if (i < NN) g_deg[i] = 0;
}

// edge_index arrives as int32; 4 edges per thread. The atomic's return value is
// the edge's rank within its row -> saved for an atomic-free scatter later.
__global__ void k_hist(const int4* __restrict__ ei4) {
    int t = blockIdx.x * blockDim.x + threadIdx.x;
    if (t < EE / 4) {
        int4 r = ei4[t];
        int4 c = ei4[EE / 4 + t];
        int e = t * 4;
        if (r.x != c.x) g_rank[e + 0] = atomicAdd(&g_deg[r.x], 1);
        if (r.y != c.y) g_rank[e + 1] = atomicAdd(&g_deg[r.y], 1);
        if (r.z != c.z) g_rank[e + 2] = atomicAdd(&g_deg[r.z], 1);
        if (r.w != c.w) g_rank[e + 3] = atomicAdd(&g_deg[r.w], 1);
    }
}

// ---- parallel 3-phase scan (phase 1 also emits dinv & sqrt(deg)) ----
__global__ void __launch_bounds__(1024) k_scan1() {
    __shared__ int warp_sums[32];
    const int tid  = threadIdx.x;
    const int lane = tid & 31;
    const int wid  = tid >> 5;
    const int i    = blockIdx.x * CHUNK + tid;
    int v = (i < NN) ? g_deg[i] : 0;
    if (i < NN) {
        g_dinv[i] = (v > 0) ? rsqrtf((float)v) : 0.0f;
        g_sd[i]   = sqrtf((float)v);
    }
    int incl = v;
    #pragma unroll
    for (int off = 1; off < 32; off <<= 1) {
        int t = __shfl_up_sync(FULL, incl, off);
        if (lane >= off) incl += t;
    }
    if (lane == 31) warp_sums[wid] = incl;
    __syncthreads();
    if (wid == 0) {
        int s  = warp_sums[lane];
        int si = s;
        #pragma unroll
        for (int off = 1; off < 32; off <<= 1) {
            int t = __shfl_up_sync(FULL, si, off);
            if (lane >= off) si += t;
        }
        warp_sums[lane] = si - s;
        if (lane == 31) g_bsum[blockIdx.x] = si;
    }
    __syncthreads();
    int excl = warp_sums[wid] + (incl - v);
    if (i < NN) g_rowptr[i] = excl;
}

__global__ void __launch_bounds__(128) k_scan2() {
    __shared__ int warp_sums[4];
    const int tid  = threadIdx.x;
    const int lane = tid & 31;
    const int wid  = tid >> 5;
    int v = (tid < NCH) ? g_bsum[tid] : 0;
    int incl = v;
    #pragma unroll
    for (int off = 1; off < 32; off <<= 1) {
        int t = __shfl_up_sync(FULL, incl, off);
        if (lane >= off) incl += t;
    }
    if (lane == 31) warp_sums[wid] = incl;
    __syncthreads();
    int carry = 0;
    #pragma unroll
    for (int w = 0; w < 4; w++)
        if (w < wid) carry += warp_sums[w];
    int excl = carry + incl - v;
    if (tid < NCH) g_boff[tid] = excl;
    if (tid == NCH - 1) g_rowptr[NN] = excl + v;
}

__global__ void __launch_bounds__(1024) k_scan3() {
    int i = blockIdx.x * CHUNK + threadIdx.x;
    if (i < NN) g_rowptr[i] += g_boff[blockIdx.x];
}

// Atomic-free scatter: pos = rowptr[row] + rank. Writes ONLY the column index.
__global__ void k_scatter(const int4* __restrict__ ei4) {
    int t = blockIdx.x * blockDim.x + threadIdx.x;
    if (t < EE / 4) {
        int4 r = ei4[t];
        int4 c = ei4[EE / 4 + t];
        int e = t * 4;
        #pragma unroll
        for (int q = 0; q < 4; q++) {
            int rr = (q == 0) ? r.x : (q == 1) ? r.y : (q == 2) ? r.z : r.w;
            int cc = (q == 0) ? c.x : (q == 1) ? c.y : (q == 2) ? c.z : c.w;
            if (rr != cc) g_col[g_rowptr[rr] + g_rank[e + q]] = cc;
        }
    }
}

// ---- x_scaled = dinv ⊙ x, stored fp16 (coalesced: thread t -> element t) ----
__global__ void __launch_bounds__(256) k_pre(const float4* __restrict__ x4) {
    int t = blockIdx.x * blockDim.x + threadIdx.x;
    if (t < NN * 8) {
        float d = g_dinv[t >> 3];
        float4 v = x4[t];
        v.x *= d; v.y *= d; v.z *= d; v.w *= d;
        ((uint2*)g_xs)[t] = pack_half4(v);
    }
}

// ---------------- single-row gather (high-occupancy k_prop) ----------------
__device__ __forceinline__ float4 gather_row(int e0, int e1, int sub, int j,
                                             const uint2* __restrict__ src) {
    float4 acc = make_float4(0.f, 0.f, 0.f, 0.f);
    int e = e0 + sub;
    for (; e + 12 < e1; e += 16) {
        int c0 = g_col[e];
        int c1 = g_col[e + 4];
        int c2 = g_col[e + 8];
        int c3 = g_col[e + 12];
        uint2 u0 = src[c0 * 8 + j];
        uint2 u1 = src[c1 * 8 + j];
        uint2 u2 = src[c2 * 8 + j];
        uint2 u3 = src[c3 * 8 + j];
        acc_add(acc, u0);
        acc_add(acc, u1);
        acc_add(acc, u2);
        acc_add(acc, u3);
    }
    for (; e + 4 < e1; e += 8) {
        int c0 = g_col[e];
        int c1 = g_col[e + 4];
        uint2 u0 = src[c0 * 8 + j];
        uint2 u1 = src[c1 * 8 + j];
        acc_add(acc, u0);
        acc_add(acc, u1);
    }
    if (e < e1) {
        uint2 u = src[g_col[e] * 8 + j];
        acc_add(acc, u);
    }
    return acc;
}

// ---------------- dual-row interleaved gather (low-occupancy epi) ----------------
// Two rows gathered together: 8 independent feature loads in flight per lane.
// Out-of-range slots clamp the index (always-valid load) and predicate the add.
__device__ __forceinline__ void gather2(int e0A, int e1A, int e0B, int e1B,
                                        int sub, int j,
                                        const uint2* __restrict__ src,
                                        float4& accA, float4& accB) {
    accA = make_float4(0.f, 0.f, 0.f, 0.f);
    accB = make_float4(0.f, 0.f, 0.f, 0.f);
    int eA = e0A + sub;
    int eB = e0B + sub;
    int itA = (e1A - e0A + 15) >> 4;
    int itB = (e1B - e0B + 15) >> 4;
    int iters = (itA > itB) ? itA : itB;
    for (int it = 0; it < iters; it++) {
        int a0 = max(min(eA,      e1A - 1), 0);
        int a1 = max(min(eA + 4,  e1A - 1), 0);
        int a2 = max(min(eA + 8,  e1A - 1), 0);
        int a3 = max(min(eA + 12, e1A - 1), 0);
        int b0 = max(min(eB,      e1B - 1), 0);
        int b1 = max(min(eB + 4,  e1B - 1), 0);
        int b2 = max(min(eB + 8,  e1B - 1), 0);
        int b3 = max(min(eB + 12, e1B - 1), 0);
        int cA0 = g_col[a0], cA1 = g_col[a1], cA2 = g_col[a2], cA3 = g_col[a3];
        int cB0 = g_col[b0], cB1 = g_col[b1], cB2 = g_col[b2], cB3 = g_col[b3];
        uint2 uA0 = src[cA0 * 8 + j];
        uint2 uA1 = src[cA1 * 8 + j];
        uint2 uA2 = src[cA2 * 8 + j];
        uint2 uA3 = src[cA3 * 8 + j];
        uint2 uB0 = src[cB0 * 8 + j];
        uint2 uB1 = src[cB1 * 8 + j];
        uint2 uB2 = src[cB2 * 8 + j];
        uint2 uB3 = src[cB3 * 8 + j];
        if (eA      < e1A) acc_add(accA, uA0);
        if (eA + 4  < e1A) acc_add(accA, uA1);
        if (eA + 8  < e1A) acc_add(accA, uA2);
        if (eA + 12 < e1A) acc_add(accA, uA3);
        if (eB      < e1B) acc_add(accB, uB0);
        if (eB + 4  < e1B) acc_add(accB, uB1);
        if (eB + 8  < e1B) acc_add(accB, uB2);
        if (eB + 12 < e1B) acc_add(accB, uB3);
        eA += 16;
        eB += 16;
    }
}

__device__ __forceinline__ void reduce_subs(float4& acc) {
    #pragma unroll
    for (int off = 8; off <= 16; off <<= 1) {
        acc.x += __shfl_xor_sync(FULL, acc.x, off);
        acc.y += __shfl_xor_sync(FULL, acc.y, off);
        acc.z += __shfl_xor_sync(FULL, acc.z, off);
        acc.w += __shfl_xor_sync(FULL, acc.w, off);
    }
}

// ---------------- prop1: t1_scaled = -dinv^2 ⊙ (sum of scaled src rows) ----------------
__global__ void __launch_bounds__(256) k_prop(const uint2* __restrict__ src,
                                              uint2* __restrict__ dst) {
    int row  = (blockIdx.x * blockDim.x + threadIdx.x) >> 5;
    int lane = threadIdx.x & 31;
    if (row >= NN) return;
    int sub = lane >> 3, j = lane & 7;
    int e0 = g_rowptr[row], e1 = g_rowptr[row + 1];
    float4 acc = gather_row(e0, e1, sub, j, src);
    reduce_subs(acc);
    float di = g_dinv[row];
    float s  = -di * di;
    if (lane < 8) {
        acc.x *= s; acc.y *= s; acc.z *= s; acc.w *= s;
        dst[row * 8 + lane] = pack_half4(acc);   // lane == j here
    }
}

// ---------------- fused prop2 + epilogue, 2 rows per warp iteration ----------------
// p_true = -dinv[row] * (sum of scaled t1 over cols);
// t1_true = t1_scaled * sqrt(deg);  out = h0@(W0-W2) + t1@W1 + p@(2W2) + b
__global__ void __launch_bounds__(256, 2) k_prop_epi(
        const uint2*  __restrict__ t1v,      // t1 SCALED fp16 (gather source)
        const __half* __restrict__ t1h,      // t1 SCALED scalar view
        const float*  __restrict__ h0,       // Tx0 rows (true, fp32)
        const float*  __restrict__ W,        // (3, 32, 32)
        const float*  __restrict__ b,
        const float*  __restrict__ resid,    // nullptr or residual rows
        float*        __restrict__ out,      // true output (fp32)
        __half*       __restrict__ outs,     // nullptr or dinv-scaled fp16 copy
        int do_relu) {
    const int lane = threadIdx.x & 31;
    const int sub  = lane >> 3, j = lane & 7;
    const int gw   = (blockIdx.x * blockDim.x + threadIdx.x) >> 5;
    const int tot  = (gridDim.x * blockDim.x) >> 5;

    // per-lane weight columns in registers
    float wc[D], w1[D], w2[D];
    #pragma unroll
    for (int i = 0; i < D; i++) {
        float a0 = W[i * D + lane];
        float a1 = W[D * D + i * D + lane];
        float a2 = W[2 * D * D + i * D + lane];
        wc[i] = a0 - a2;
        w1[i] = a1;
        w2[i] = 2.0f * a2;
    }
    const float bias = b[lane];

    for (int rp = gw; rp < NN / 2; rp += tot) {
        const int rowA = rp * 2;
        const int rowB = rowA + 1;
        int e0A = g_rowptr[rowA], e1A = g_rowptr[rowA + 1];
        int e0B = e1A,            e1B = g_rowptr[rowB + 1];
        float4 accA, accB;
        gather2(e0A, e1A, e0B, e1B, sub, j, t1v, accA, accB);
        reduce_subs(accA);
        reduce_subs(accB);
        #pragma unroll
        for (int half = 0; half < 2; half++) {
            const int row = (half == 0) ? rowA : rowB;
            float4 acc   = (half == 0) ? accA : accB;
            float di = g_dinv[row];
            float sd = g_sd[row];
            float nd = -di;
            acc.x *= nd; acc.y *= nd; acc.z *= nd; acc.w *= nd;   // p_true chunk
            float hv = h0[row * D + lane];
            float tv = __half2float(t1h[row * D + lane]) * sd;     // unscale t1
            float o = bias;
            #pragma unroll
            for (int i = 0; i < D; i++) {
                float hi = __shfl_sync(FULL, hv, i);
                float ti = __shfl_sync(FULL, tv, i);
                float comp = ((i & 3) == 0) ? acc.x :
                             ((i & 3) == 1) ? acc.y :
                             ((i & 3) == 2) ? acc.z : acc.w;
                float pi = __shfl_sync(FULL, comp, i >> 2);
                o = fmaf(hi, wc[i], o);
                o = fmaf(ti, w1[i], o);
                o = fmaf(pi, w2[i], o);
            }
            if (do_relu) o = fmaxf(o, 0.0f);
            if (resid)   o += resid[row * D + lane];
            out[row * D + lane] = o;
            if (outs) outs[row * D + lane] = __float2half(di * o);
        }
    }
}

// ---------------- launch ----------------
extern "C" void kernel_launch(void* const* d_in, const int* in_sizes, int n_in,
                              void* d_out, int out_size) {
    const float* x  = (const float*)d_in[0];
    const int*   ei = (const int*)d_in[1];       // int32 edge_index (2, E)
    const float* W1 = (const float*)d_in[2];
    const float* b1 = (const float*)d_in[3];
    const float* W2 = (const float*)d_in[4];
    const float* b2 = (const float*)d_in[5];
    float*       out = (float*)d_out;

    void *p_xs, *p_h, *p_hs, *p_t1;
    cudaGetSymbolAddress(&p_xs, g_xs);
    cudaGetSymbolAddress(&p_h,  g_h);
    cudaGetSymbolAddress(&p_hs, g_hs);
    cudaGetSymbolAddress(&p_t1, g_t1);

    const int TB = 256;
    int gN  = (NN + TB - 1) / TB;
    int gE4 = (EE / 4 + TB - 1) / TB;
    int gV  = (NN * 8 + TB - 1) / TB;  // 4-float chunks
    int gProp = (NN + 7) / 8;          // one warp per row
    int gFuse = 296;                   // 148 SMs * 2 resident CTAs

    // ---- CSR build (col-only) ----
    k_zero_deg<<<gN, TB>>>();
    k_hist<<<gE4, TB>>>((const int4*)ei);
    k_scan1<<<NCH, 1024>>>();
    k_scan2<<<1, 128>>>();
    k_scan3<<<NCH, 1024>>>();
    k_scatter<<<gE4, TB>>>((const int4*)ei);
    k_pre<<<gV, TB>>>((const float4*)x);

    // ---- layer 1: h = relu(cheb(x; W1,b1)), plus scaled fp16 copy hs ----
    k_prop<<<gProp, TB>>>((const uint2*)p_xs, (uint2*)p_t1);
    k_prop_epi<<<gFuse, TB>>>((const uint2*)p_t1, (const __half*)p_t1,
                              x, W1, b1, (const float*)nullptr,
                              (float*)p_h, (__half*)p_hs, 1);

    // ---- layer 2 + residual: out = cheb(h; W2,b2) + x ----
    k_prop<<<gProp, TB>>>((const uint2*)p_hs, (uint2*)p_t1);
    k_prop_epi<<<gFuse, TB>>>((const uint2*)p_t1, (const __half*)p_t1,
                              (const float*)p_h, W2, b2,
                              x, out, (__half*)nullptr, 0);
}